// round 1
// baseline (speedup 1.0000x reference)
#include <cuda_runtime.h>
#include <cstdint>

#define TT   3072
#define HID  4096
#define NH   32
#define HD   128
#define NBAT 4
#define MAXB 24

// ---- workspace (static device arrays; no allocation) ----
__device__ float g_q[(size_t)TT * HID];
__device__ float g_k[(size_t)TT * HID];
__device__ float g_v[(size_t)TT * HID];
__device__ float g_o[(size_t)TT * HID];
__device__ float g_freq[64];

__global__ void init_freq_kernel() {
    int i = threadIdx.x;
    if (i < 64) g_freq[i] = (float)exp(-(double)i * (log(10000.0) / 64.0));
}

// ============================================================================
// SGEMM: C[M,N] = A[M,K] @ B[N,K]^T + bias   (M=3072, N=K=4096)
// 128x128 tile, BK=16, 256 threads, 8x8 per thread (4x4 quadrants).
// ============================================================================
__global__ __launch_bounds__(256) void sgemm_bias(
    const float* __restrict__ A, const float* __restrict__ B,
    const float* __restrict__ bias, float* __restrict__ C)
{
    __shared__ float As[16][128];
    __shared__ float Bs[16][128];
    const int tid = threadIdx.x;
    const int tx = tid & 15;
    const int ty = tid >> 4;
    const int m0 = blockIdx.y * 128;
    const int n0 = blockIdx.x * 128;
    const int lrow = tid >> 2;          // 0..63
    const int lk = (tid & 3) << 2;      // 0,4,8,12

    float acc[8][8];
#pragma unroll
    for (int i = 0; i < 8; i++)
#pragma unroll
        for (int j = 0; j < 8; j++) acc[i][j] = 0.f;

    const float* Arow0 = A + (size_t)(m0 + lrow) * HID + lk;
    const float* Arow1 = A + (size_t)(m0 + lrow + 64) * HID + lk;
    const float* Brow0 = B + (size_t)(n0 + lrow) * HID + lk;
    const float* Brow1 = B + (size_t)(n0 + lrow + 64) * HID + lk;

    for (int k0 = 0; k0 < HID; k0 += 16) {
        float4 a0 = *(const float4*)(Arow0 + k0);
        float4 a1 = *(const float4*)(Arow1 + k0);
        float4 b0 = *(const float4*)(Brow0 + k0);
        float4 b1 = *(const float4*)(Brow1 + k0);
        __syncthreads();
        As[lk+0][lrow]    = a0.x; As[lk+1][lrow]    = a0.y; As[lk+2][lrow]    = a0.z; As[lk+3][lrow]    = a0.w;
        As[lk+0][lrow+64] = a1.x; As[lk+1][lrow+64] = a1.y; As[lk+2][lrow+64] = a1.z; As[lk+3][lrow+64] = a1.w;
        Bs[lk+0][lrow]    = b0.x; Bs[lk+1][lrow]    = b0.y; Bs[lk+2][lrow]    = b0.z; Bs[lk+3][lrow]    = b0.w;
        Bs[lk+0][lrow+64] = b1.x; Bs[lk+1][lrow+64] = b1.y; Bs[lk+2][lrow+64] = b1.z; Bs[lk+3][lrow+64] = b1.w;
        __syncthreads();
#pragma unroll
        for (int kk = 0; kk < 16; kk++) {
            float ar[8], br[8];
            *(float4*)&ar[0] = *(const float4*)&As[kk][ty << 2];
            *(float4*)&ar[4] = *(const float4*)&As[kk][64 + (ty << 2)];
            *(float4*)&br[0] = *(const float4*)&Bs[kk][tx << 2];
            *(float4*)&br[4] = *(const float4*)&Bs[kk][64 + (tx << 2)];
#pragma unroll
            for (int i = 0; i < 8; i++)
#pragma unroll
                for (int j = 0; j < 8; j++)
                    acc[i][j] += ar[i] * br[j];
        }
    }

    float bl[4], bh[4];
    *(float4*)bl = *(const float4*)&bias[n0 + (tx << 2)];
    *(float4*)bh = *(const float4*)&bias[n0 + 64 + (tx << 2)];
#pragma unroll
    for (int i = 0; i < 8; i++) {
        int row = m0 + ((i < 4) ? (ty * 4 + i) : (64 + ty * 4 + i - 4));
        float4 c0, c1;
        c0.x = acc[i][0] + bl[0]; c0.y = acc[i][1] + bl[1];
        c0.z = acc[i][2] + bl[2]; c0.w = acc[i][3] + bl[3];
        c1.x = acc[i][4] + bh[0]; c1.y = acc[i][5] + bh[1];
        c1.z = acc[i][6] + bh[2]; c1.w = acc[i][7] + bh[3];
        *(float4*)&C[(size_t)row * HID + n0 + (tx << 2)]      = c0;
        *(float4*)&C[(size_t)row * HID + n0 + 64 + (tx << 2)] = c1;
    }
}

// ============================================================================
// RoPE on packed q,k in place. Angle rounded to f32 like the reference
// (f = pos * inv in f32), trig done in double (robust to fast-math).
// ============================================================================
__global__ void rope_kernel(const int* __restrict__ pos) {
    int idx = blockIdx.x * blockDim.x + threadIdx.x;
    if (idx >= TT * NH * 64) return;
    int i = idx & 63;
    int h = (idx >> 6) & 31;
    int t = idx >> 11;
    float p = (float)pos[t];
    float ang = p * g_freq[i];              // f32 product, like reference
    double ad = (double)ang;
    float c = (float)cos(ad);
    float s = (float)sin(ad);
    size_t base = ((size_t)t * NH + h) * HD;
    float x1 = g_q[base + i], x2 = g_q[base + 64 + i];
    g_q[base + i]      = x1 * c - x2 * s;
    g_q[base + 64 + i] = x2 * c + x1 * s;
    float y1 = g_k[base + i], y2 = g_k[base + 64 + i];
    g_k[base + i]      = y1 * c - y2 * s;
    g_k[base + 64 + i] = y2 * c + y1 * s;
}

// ============================================================================
// Flash attention (fp32). One CTA = (q-tile of 64, head, batch), 128 threads.
// K/V read directly from paged cache (history) or fresh k/v (new tokens) —
// equivalent to scatter+gather since block tables don't alias here.
// ============================================================================
#define ATTN_SMEM_FLOATS (8192 + 8448 + 4224 + 192)
#define ATTN_SMEM_BYTES  (ATTN_SMEM_FLOATS * 4)

__global__ __launch_bounds__(128) void attn_kernel(
    const float* __restrict__ past_k, const float* __restrict__ past_v,
    const int* __restrict__ q_start, const int* __restrict__ q_lens,
    const int* __restrict__ kv_lens, const int* __restrict__ boff)
{
    extern __shared__ float sm[];
    float* Qs   = sm;                 // 64 x 128
    float* KVs  = sm + 8192;          // 64 x 132  (K, then reused for V)
    float* Ps   = KVs + 8448;         // 64 x 66
    float* mrow = Ps + 4224;          // 64
    float* lrow = mrow + 64;          // 64
    float* arow = lrow + 64;          // 64

    const int b = blockIdx.z, h = blockIdx.y, qt = blockIdx.x;
    const int qlen = q_lens[b];
    if (qt * 64 >= qlen) return;
    const int qs0 = q_start[b];
    const int kvlen = kv_lens[b];
    const int hist = kvlen - qlen;
    const int tid = threadIdx.x;
    const float scale = 0.08838834764831845f;
    const float NEGINF = __int_as_float(0xff800000);

    const int c4 = (tid & 31) << 2;   // dim offset for loads
    const int r0 = tid >> 5;          // base row for loads

    // ---- load Q tile ----
#pragma unroll
    for (int rr = 0; rr < 16; rr++) {
        int r = r0 + rr * 4;
        int qglob = qt * 64 + r;
        float4 v = make_float4(0.f, 0.f, 0.f, 0.f);
        if (qglob < qlen)
            v = *(const float4*)&g_q[((size_t)(qs0 + qglob) * NH + h) * HD + c4];
        *(float4*)&Qs[r * 128 + c4] = v;
    }
    if (tid < 64) { mrow[tid] = NEGINF; lrow[tid] = 0.f; }
    __syncthreads();

    const int tq = tid >> 3;   // 0..15 : q rows 4tq..4tq+3
    const int tk = tid & 7;    // 0..7  : S cols tk+8m ; PV dims 4tk+32m

    float o[4][16];
#pragma unroll
    for (int i = 0; i < 4; i++)
#pragma unroll
        for (int j = 0; j < 16; j++) o[i][j] = 0.f;

    const int qhi  = min(qt * 64 + 63, qlen - 1);
    const int nblk = min((kvlen + 63) >> 6, ((hist + qhi) >> 6) + 1);

    for (int kb = 0; kb < nblk; kb++) {
        // ---- load K tile (row-major, stride 132) ----
#pragma unroll
        for (int rr = 0; rr < 16; rr++) {
            int r = r0 + rr * 4;
            int p = kb * 64 + r;
            int pc = min(p, kvlen - 1);
            const float* src;
            if (pc < hist) {
                int blk = boff[b * MAXB + (pc >> 6)];
                src = past_k + ((size_t)(blk * 64 + (pc & 63)) * NH + h) * HD;
            } else {
                src = g_k + ((size_t)(qs0 + pc - hist) * NH + h) * HD;
            }
            *(float4*)&KVs[r * 132 + c4] = *(const float4*)&src[c4];
        }
        __syncthreads();

        // ---- S = Q K^T (4q x 8k per thread) ----
        float s[4][8];
#pragma unroll
        for (int i = 0; i < 4; i++)
#pragma unroll
            for (int m = 0; m < 8; m++) s[i][m] = 0.f;
#pragma unroll 4
        for (int d = 0; d < 128; d += 4) {
            float4 qv[4];
#pragma unroll
            for (int i = 0; i < 4; i++)
                qv[i] = *(const float4*)&Qs[(tq * 4 + i) * 128 + d];
#pragma unroll
            for (int m = 0; m < 8; m++) {
                float4 kv = *(const float4*)&KVs[(tk + 8 * m) * 132 + d];
#pragma unroll
                for (int i = 0; i < 4; i++)
                    s[i][m] += qv[i].x * kv.x + qv[i].y * kv.y + qv[i].z * kv.z + qv[i].w * kv.w;
            }
        }
        // mask + store scores
#pragma unroll
        for (int i = 0; i < 4; i++) {
            int qglob = qt * 64 + tq * 4 + i;
#pragma unroll
            for (int m = 0; m < 8; m++) {
                int kg = kb * 64 + tk + 8 * m;
                float val = (kg <= hist + qglob) ? s[i][m] * scale : NEGINF;
                Ps[(tq * 4 + i) * 66 + tk + 8 * m] = val;
            }
        }
        __syncthreads();

        // ---- load V tile into the same buffer ----
#pragma unroll
        for (int rr = 0; rr < 16; rr++) {
            int r = r0 + rr * 4;
            int p = kb * 64 + r;
            int pc = min(p, kvlen - 1);
            const float* src;
            if (pc < hist) {
                int blk = boff[b * MAXB + (pc >> 6)];
                src = past_v + ((size_t)(blk * 64 + (pc & 63)) * NH + h) * HD;
            } else {
                src = g_v + ((size_t)(qs0 + pc - hist) * NH + h) * HD;
            }
            *(float4*)&KVs[r * 132 + c4] = *(const float4*)&src[c4];
        }

        // ---- online softmax (one thread per q row) ----
        if (tid < 64) {
            int r = tid;
            float mo = mrow[r];
            float mx = mo;
#pragma unroll 8
            for (int j = 0; j < 64; j++) mx = fmaxf(mx, Ps[r * 66 + j]);
            float alpha = expf(mo - mx);    // mo=-inf on first block -> 0
            float sum = 0.f;
#pragma unroll 8
            for (int j = 0; j < 64; j++) {
                float pj = expf(Ps[r * 66 + j] - mx);
                Ps[r * 66 + j] = pj;
                sum += pj;
            }
            mrow[r] = mx;
            lrow[r] = lrow[r] * alpha + sum;
            arow[r] = alpha;
        }
        __syncthreads();

        // ---- O = O*alpha + P V  (4q x 16d per thread, dims 4tk+32m) ----
#pragma unroll
        for (int i = 0; i < 4; i++) {
            float a = arow[tq * 4 + i];
#pragma unroll
            for (int j = 0; j < 16; j++) o[i][j] *= a;
        }
#pragma unroll 2
        for (int k = 0; k < 64; k++) {
            float pr[4];
#pragma unroll
            for (int i = 0; i < 4; i++) pr[i] = Ps[(tq * 4 + i) * 66 + k];
#pragma unroll
            for (int m = 0; m < 4; m++) {
                float4 vv = *(const float4*)&KVs[k * 132 + tk * 4 + 32 * m];
#pragma unroll
                for (int i = 0; i < 4; i++) {
                    o[i][m * 4 + 0] += pr[i] * vv.x;
                    o[i][m * 4 + 1] += pr[i] * vv.y;
                    o[i][m * 4 + 2] += pr[i] * vv.z;
                    o[i][m * 4 + 3] += pr[i] * vv.w;
                }
            }
        }
        __syncthreads();   // protect KVs/Ps before next block
    }

    // ---- epilogue ----
#pragma unroll
    for (int i = 0; i < 4; i++) {
        int qglob = qt * 64 + tq * 4 + i;
        if (qglob >= qlen) continue;
        float inv = 1.f / lrow[tq * 4 + i];
        size_t base = ((size_t)(qs0 + qglob) * NH + h) * HD;
#pragma unroll
        for (int m = 0; m < 4; m++) {
            float4 w;
            w.x = o[i][m * 4 + 0] * inv;
            w.y = o[i][m * 4 + 1] * inv;
            w.z = o[i][m * 4 + 2] * inv;
            w.w = o[i][m * 4 + 3] * inv;
            *(float4*)&g_o[base + tk * 4 + 32 * m] = w;
        }
    }
}

// ============================================================================
extern "C" void kernel_launch(void* const* d_in, const int* in_sizes, int n_in,
                              void* d_out, int out_size) {
    const float* x      = (const float*)d_in[0];
    const int*   pos    = (const int*)d_in[1];
    const int*   qstart = (const int*)d_in[2];
    const int*   qlens  = (const int*)d_in[3];
    const int*   kvlens = (const int*)d_in[4];
    const int*   boff   = (const int*)d_in[5];
    const float* pk     = (const float*)d_in[6];
    const float* pv     = (const float*)d_in[7];
    const float* Wq = (const float*)d_in[8];
    const float* bq = (const float*)d_in[9];
    const float* Wk = (const float*)d_in[10];
    const float* bk = (const float*)d_in[11];
    const float* Wv = (const float*)d_in[12];
    const float* bv = (const float*)d_in[13];
    const float* Wo = (const float*)d_in[14];
    const float* bo = (const float*)d_in[15];
    float* out = (float*)d_out;

    float *qp, *kp, *vp, *op;
    cudaGetSymbolAddress((void**)&qp, g_q);
    cudaGetSymbolAddress((void**)&kp, g_k);
    cudaGetSymbolAddress((void**)&vp, g_v);
    cudaGetSymbolAddress((void**)&op, g_o);

    dim3 gg(HID / 128, TT / 128);   // (32, 24)
    sgemm_bias<<<gg, 256>>>(x, Wq, bq, qp);
    sgemm_bias<<<gg, 256>>>(x, Wk, bk, kp);
    sgemm_bias<<<gg, 256>>>(x, Wv, bv, vp);

    init_freq_kernel<<<1, 64>>>();
    rope_kernel<<<(TT * NH * 64 + 255) / 256, 256>>>(pos);

    cudaFuncSetAttribute(attn_kernel, cudaFuncAttributeMaxDynamicSharedMemorySize,
                         ATTN_SMEM_BYTES);
    attn_kernel<<<dim3(16, NH, NBAT), 128, ATTN_SMEM_BYTES>>>(pk, pv, qstart, qlens,
                                                              kvlens, boff);

    sgemm_bias<<<gg, 256>>>(op, Wo, bo, out);
}

// round 3
// speedup vs baseline: 1.8587x; 1.8587x over previous
#include <cuda_runtime.h>
#include <cuda_bf16.h>
#include <cstdint>

#define TT   3072
#define HID  4096
#define NH   32
#define HD   128
#define NBAT 4
#define MAXB 24

// ============================================================================
// helpers (baseline PTX only — no sm_103a-gated features)
// ============================================================================
__device__ __forceinline__ uint32_t smem_to_u32(const void* p) {
    uint32_t a;
    asm("{ .reg .u64 t; cvta.to.shared.u64 t, %1; cvt.u32.u64 %0, t; }" : "=r"(a) : "l"(p));
    return a;
}
__device__ __forceinline__ void cp16(uint32_t dst, const void* src) {
    asm volatile("cp.async.cg.shared.global [%0], [%1], 16;" :: "r"(dst), "l"(src));
}
#define CP_COMMIT() asm volatile("cp.async.commit_group;" ::: "memory")
#define CP_WAIT2()  asm volatile("cp.async.wait_group 2;" ::: "memory")

__device__ __forceinline__ void ldsm4(uint32_t* r, uint32_t addr) {
    asm volatile("ldmatrix.sync.aligned.m8n8.x4.shared.b16 {%0,%1,%2,%3}, [%4];"
        : "=r"(r[0]), "=r"(r[1]), "=r"(r[2]), "=r"(r[3]) : "r"(addr));
}
__device__ __forceinline__ void mma_bf16(float* c, const uint32_t* a, const uint32_t* b) {
    asm volatile("mma.sync.aligned.m16n8k16.row.col.f32.bf16.bf16.f32 "
        "{%0,%1,%2,%3}, {%4,%5,%6,%7}, {%8,%9}, {%0,%1,%2,%3};"
        : "+f"(c[0]), "+f"(c[1]), "+f"(c[2]), "+f"(c[3])
        : "r"(a[0]), "r"(a[1]), "r"(a[2]), "r"(a[3]), "r"(b[0]), "r"(b[1]));
}

// ---- workspace (static device arrays; no allocation) ----
__device__ float g_q[(size_t)TT * HID];
__device__ float g_k[(size_t)TT * HID];
__device__ float g_v[(size_t)TT * HID];
__device__ float g_o[(size_t)TT * HID];
__device__ float g_freq[64];
__device__ __nv_bfloat16 g_xhi[(size_t)TT * HID];
__device__ __nv_bfloat16 g_xlo[(size_t)TT * HID];
__device__ __nv_bfloat16 g_w1hi[(size_t)HID * HID];
__device__ __nv_bfloat16 g_w1lo[(size_t)HID * HID];
__device__ __nv_bfloat16 g_w2hi[(size_t)HID * HID];
__device__ __nv_bfloat16 g_w2lo[(size_t)HID * HID];
__device__ __nv_bfloat16 g_w3hi[(size_t)HID * HID];
__device__ __nv_bfloat16 g_w3lo[(size_t)HID * HID];

__global__ void init_freq_kernel() {
    int i = threadIdx.x;
    if (i < 64) g_freq[i] = (float)exp(-(double)i * (log(10000.0) / 64.0));
}

// ============================================================================
// fp32 -> bf16 hi/lo split (vectorized by 4)
// ============================================================================
__global__ __launch_bounds__(256) void split_kernel(
    const float* __restrict__ x, __nv_bfloat16* __restrict__ hi,
    __nv_bfloat16* __restrict__ lo, int n4)
{
    int i = blockIdx.x * blockDim.x + threadIdx.x;
    if (i >= n4) return;
    float4 v = ((const float4*)x)[i];
    float vv[4] = {v.x, v.y, v.z, v.w};
    __nv_bfloat16 h[4], l[4];
#pragma unroll
    for (int j = 0; j < 4; j++) {
        h[j] = __float2bfloat16(vv[j]);
        l[j] = __float2bfloat16(vv[j] - __bfloat162float(h[j]));
    }
    ((__nv_bfloat162*)hi)[2 * i + 0] = __nv_bfloat162(h[0], h[1]);
    ((__nv_bfloat162*)hi)[2 * i + 1] = __nv_bfloat162(h[2], h[3]);
    ((__nv_bfloat162*)lo)[2 * i + 0] = __nv_bfloat162(l[0], l[1]);
    ((__nv_bfloat162*)lo)[2 * i + 1] = __nv_bfloat162(l[2], l[3]);
}

// ============================================================================
// mma.sync GEMM: C[3072,4096] = A @ B^T + bias, 3-term bf16 split.
// CTA 128x128, BK=64, 8 warps (2x4), warp tile 64x32, cp.async 3-stage.
// SMEM stage = 4 tiles (Ahi, Alo, Bhi, Blo), each 128 rows x 128B, SW128 XOR.
// ============================================================================
#define STAGES  3
#define TILE_B  16384
#define STAGE_B (4 * TILE_B)
#define GEMM_SMEM (STAGES * STAGE_B)   // 196608

__global__ __launch_bounds__(256)
void gemm3(const __nv_bfloat16* __restrict__ Ahi, const __nv_bfloat16* __restrict__ Alo,
           const __nv_bfloat16* __restrict__ Bhi, const __nv_bfloat16* __restrict__ Blo,
           const float* __restrict__ bias, float* __restrict__ C)
{
    extern __shared__ char smem[];
    const uint32_t sb = smem_to_u32(smem);
    const int tid = threadIdx.x;
    const int wid = tid >> 5;
    const int lane = tid & 31;
    const int m0 = blockIdx.y << 7;
    const int n0 = blockIdx.x << 7;
    const int wm = wid >> 2;        // 0..1
    const int wn = wid & 3;         // 0..3

    // ---- loader setup: 2 threads per row, 4x16B each, 4 tiles ----
    const int lrow = tid >> 1;              // 0..127
    const int lcb  = (tid & 1) * 4;         // 16B-chunk base 0 or 4
    const uint32_t lrsw = (uint32_t)(lrow & 7) << 4;
    const __nv_bfloat16* gsrc[4];
    gsrc[0] = Ahi + (size_t)(m0 + lrow) * HID + lcb * 8;
    gsrc[1] = Alo + (size_t)(m0 + lrow) * HID + lcb * 8;
    gsrc[2] = Bhi + (size_t)(n0 + lrow) * HID + lcb * 8;
    gsrc[3] = Blo + (size_t)(n0 + lrow) * HID + lcb * 8;
    uint32_t ldst[4][4];
#pragma unroll
    for (int t = 0; t < 4; t++)
#pragma unroll
        for (int j = 0; j < 4; j++)
            ldst[t][j] = t * TILE_B + lrow * 128 + ((uint32_t)((lcb + j) * 16) ^ lrsw);

    // ---- fragment address setup ----
    uint32_t a_off[4], a_sw[4];
#pragma unroll
    for (int mt = 0; mt < 4; mt++) {
        int m = wm * 64 + mt * 16 + (lane & 15);
        a_off[mt] = (uint32_t)m * 128;
        a_sw[mt]  = (uint32_t)(m & 7) << 4;
    }
    const uint32_t ka = (uint32_t)((lane >> 4) << 4);   // 0 | 16
    uint32_t b_off[2], b_sw[2];
#pragma unroll
    for (int p = 0; p < 2; p++) {
        int n = wn * 32 + p * 16 + (lane & 7) + ((lane & 16) >> 1);
        b_off[p] = (uint32_t)n * 128;
        b_sw[p]  = (uint32_t)(n & 7) << 4;
    }
    const uint32_t kb = (uint32_t)((lane & 8) << 1);    // 0 | 16

    float acc[4][4][4];
#pragma unroll
    for (int i = 0; i < 4; i++)
#pragma unroll
        for (int j = 0; j < 4; j++)
#pragma unroll
            for (int k = 0; k < 4; k++) acc[i][j][k] = 0.f;

    // ---- prologue: load chunks 0,1 ----
#pragma unroll
    for (int s = 0; s < 2; s++) {
        uint32_t base = sb + s * STAGE_B;
#pragma unroll
        for (int t = 0; t < 4; t++) {
            const __nv_bfloat16* src = gsrc[t] + s * 64;
#pragma unroll
            for (int j = 0; j < 4; j++)
                cp16(base + ldst[t][j], src + j * 8);
        }
        CP_COMMIT();
    }

    for (int c = 0; c < 64; c++) {
        const int ldc = c + 2;
        if (ldc < 64) {
            uint32_t base = sb + (ldc % 3) * STAGE_B;
#pragma unroll
            for (int t = 0; t < 4; t++) {
                const __nv_bfloat16* src = gsrc[t] + ldc * 64;
#pragma unroll
                for (int j = 0; j < 4; j++)
                    cp16(base + ldst[t][j], src + j * 8);
            }
        }
        CP_COMMIT();
        CP_WAIT2();
        __syncthreads();

        const uint32_t stb = sb + (c % 3) * STAGE_B;
#pragma unroll
        for (int ks = 0; ks < 4; ks++) {
            uint32_t ahi[4][4], alo[4][4];
#pragma unroll
            for (int mt = 0; mt < 4; mt++) {
                uint32_t ko = ((uint32_t)(ks * 32) + ka) ^ a_sw[mt];
                uint32_t ad = stb + a_off[mt] + ko;
                ldsm4(ahi[mt], ad);
                ldsm4(alo[mt], ad + TILE_B);
            }
            uint32_t bhi[2][4], blo[2][4];
#pragma unroll
            for (int p = 0; p < 2; p++) {
                uint32_t ko = ((uint32_t)(ks * 32) + kb) ^ b_sw[p];
                uint32_t bd = stb + 2 * TILE_B + b_off[p] + ko;
                ldsm4(bhi[p], bd);
                ldsm4(blo[p], bd + TILE_B);
            }
#pragma unroll
            for (int mt = 0; mt < 4; mt++)
#pragma unroll
                for (int nt = 0; nt < 4; nt++) {
                    const uint32_t* bh = &bhi[nt >> 1][2 * (nt & 1)];
                    const uint32_t* bl = &blo[nt >> 1][2 * (nt & 1)];
                    mma_bf16(acc[mt][nt], ahi[mt], bh);
                    mma_bf16(acc[mt][nt], ahi[mt], bl);
                    mma_bf16(acc[mt][nt], alo[mt], bh);
                }
        }
        __syncthreads();
    }

    // ---- epilogue: bias add + store ----
#pragma unroll
    for (int mt = 0; mt < 4; mt++) {
#pragma unroll
        for (int nt = 0; nt < 4; nt++) {
            int row = m0 + wm * 64 + mt * 16 + (lane >> 2);
            int col = n0 + wn * 32 + nt * 8 + 2 * (lane & 3);
            float2 bv = *(const float2*)&bias[col];
            float2 v0, v1;
            v0.x = acc[mt][nt][0] + bv.x; v0.y = acc[mt][nt][1] + bv.y;
            v1.x = acc[mt][nt][2] + bv.x; v1.y = acc[mt][nt][3] + bv.y;
            *(float2*)&C[(size_t)row * HID + col]       = v0;
            *(float2*)&C[(size_t)(row + 8) * HID + col] = v1;
        }
    }
}

// ============================================================================
// RoPE on packed q,k in place (angle in f32 like reference, trig in double)
// ============================================================================
__global__ void rope_kernel(const int* __restrict__ pos) {
    int idx = blockIdx.x * blockDim.x + threadIdx.x;
    if (idx >= TT * NH * 64) return;
    int i = idx & 63;
    int h = (idx >> 6) & 31;
    int t = idx >> 11;
    float p = (float)pos[t];
    float ang = p * g_freq[i];
    double ad = (double)ang;
    float c = (float)cos(ad);
    float s = (float)sin(ad);
    size_t base = ((size_t)t * NH + h) * HD;
    float x1 = g_q[base + i], x2 = g_q[base + 64 + i];
    g_q[base + i]      = x1 * c - x2 * s;
    g_q[base + 64 + i] = x2 * c + x1 * s;
    float y1 = g_k[base + i], y2 = g_k[base + 64 + i];
    g_k[base + i]      = y1 * c - y2 * s;
    g_k[base + 64 + i] = y2 * c + y1 * s;
}

// ============================================================================
// Flash attention (fp32), validated in round 1
// ============================================================================
#define ATTN_SMEM_FLOATS (8192 + 8448 + 4224 + 192)
#define ATTN_SMEM_BYTES  (ATTN_SMEM_FLOATS * 4)

__global__ __launch_bounds__(128) void attn_kernel(
    const float* __restrict__ past_k, const float* __restrict__ past_v,
    const int* __restrict__ q_start, const int* __restrict__ q_lens,
    const int* __restrict__ kv_lens, const int* __restrict__ boff)
{
    extern __shared__ float sm[];
    float* Qs   = sm;
    float* KVs  = sm + 8192;
    float* Ps   = KVs + 8448;
    float* mrow = Ps + 4224;
    float* lrow = mrow + 64;
    float* arow = lrow + 64;

    const int b = blockIdx.z, h = blockIdx.y, qt = blockIdx.x;
    const int qlen = q_lens[b];
    if (qt * 64 >= qlen) return;
    const int qs0 = q_start[b];
    const int kvlen = kv_lens[b];
    const int hist = kvlen - qlen;
    const int tid = threadIdx.x;
    const float scale = 0.08838834764831845f;
    const float NEGINF = __int_as_float(0xff800000);

    const int c4 = (tid & 31) << 2;
    const int r0 = tid >> 5;

#pragma unroll
    for (int rr = 0; rr < 16; rr++) {
        int r = r0 + rr * 4;
        int qglob = qt * 64 + r;
        float4 v = make_float4(0.f, 0.f, 0.f, 0.f);
        if (qglob < qlen)
            v = *(const float4*)&g_q[((size_t)(qs0 + qglob) * NH + h) * HD + c4];
        *(float4*)&Qs[r * 128 + c4] = v;
    }
    if (tid < 64) { mrow[tid] = NEGINF; lrow[tid] = 0.f; }
    __syncthreads();

    const int tq = tid >> 3;
    const int tk = tid & 7;

    float o[4][16];
#pragma unroll
    for (int i = 0; i < 4; i++)
#pragma unroll
        for (int j = 0; j < 16; j++) o[i][j] = 0.f;

    const int qhi  = min(qt * 64 + 63, qlen - 1);
    const int nblk = min((kvlen + 63) >> 6, ((hist + qhi) >> 6) + 1);

    for (int kb = 0; kb < nblk; kb++) {
#pragma unroll
        for (int rr = 0; rr < 16; rr++) {
            int r = r0 + rr * 4;
            int p = kb * 64 + r;
            int pc = min(p, kvlen - 1);
            const float* src;
            if (pc < hist) {
                int blk = boff[b * MAXB + (pc >> 6)];
                src = past_k + ((size_t)(blk * 64 + (pc & 63)) * NH + h) * HD;
            } else {
                src = g_k + ((size_t)(qs0 + pc - hist) * NH + h) * HD;
            }
            *(float4*)&KVs[r * 132 + c4] = *(const float4*)&src[c4];
        }
        __syncthreads();

        float s[4][8];
#pragma unroll
        for (int i = 0; i < 4; i++)
#pragma unroll
            for (int m = 0; m < 8; m++) s[i][m] = 0.f;
#pragma unroll 4
        for (int d = 0; d < 128; d += 4) {
            float4 qv[4];
#pragma unroll
            for (int i = 0; i < 4; i++)
                qv[i] = *(const float4*)&Qs[(tq * 4 + i) * 128 + d];
#pragma unroll
            for (int m = 0; m < 8; m++) {
                float4 kv = *(const float4*)&KVs[(tk + 8 * m) * 132 + d];
#pragma unroll
                for (int i = 0; i < 4; i++)
                    s[i][m] += qv[i].x * kv.x + qv[i].y * kv.y + qv[i].z * kv.z + qv[i].w * kv.w;
            }
        }
#pragma unroll
        for (int i = 0; i < 4; i++) {
            int qglob = qt * 64 + tq * 4 + i;
#pragma unroll
            for (int m = 0; m < 8; m++) {
                int kg = kb * 64 + tk + 8 * m;
                float val = (kg <= hist + qglob) ? s[i][m] * scale : NEGINF;
                Ps[(tq * 4 + i) * 66 + tk + 8 * m] = val;
            }
        }
        __syncthreads();

#pragma unroll
        for (int rr = 0; rr < 16; rr++) {
            int r = r0 + rr * 4;
            int p = kb * 64 + r;
            int pc = min(p, kvlen - 1);
            const float* src;
            if (pc < hist) {
                int blk = boff[b * MAXB + (pc >> 6)];
                src = past_v + ((size_t)(blk * 64 + (pc & 63)) * NH + h) * HD;
            } else {
                src = g_v + ((size_t)(qs0 + pc - hist) * NH + h) * HD;
            }
            *(float4*)&KVs[r * 132 + c4] = *(const float4*)&src[c4];
        }

        if (tid < 64) {
            int r = tid;
            float mo = mrow[r];
            float mx = mo;
#pragma unroll 8
            for (int j = 0; j < 64; j++) mx = fmaxf(mx, Ps[r * 66 + j]);
            float alpha = expf(mo - mx);
            float sum = 0.f;
#pragma unroll 8
            for (int j = 0; j < 64; j++) {
                float pj = expf(Ps[r * 66 + j] - mx);
                Ps[r * 66 + j] = pj;
                sum += pj;
            }
            mrow[r] = mx;
            lrow[r] = lrow[r] * alpha + sum;
            arow[r] = alpha;
        }
        __syncthreads();

#pragma unroll
        for (int i = 0; i < 4; i++) {
            float a = arow[tq * 4 + i];
#pragma unroll
            for (int j = 0; j < 16; j++) o[i][j] *= a;
        }
#pragma unroll 2
        for (int k = 0; k < 64; k++) {
            float pr[4];
#pragma unroll
            for (int i = 0; i < 4; i++) pr[i] = Ps[(tq * 4 + i) * 66 + k];
#pragma unroll
            for (int m = 0; m < 4; m++) {
                float4 vv = *(const float4*)&KVs[k * 132 + tk * 4 + 32 * m];
#pragma unroll
                for (int i = 0; i < 4; i++) {
                    o[i][m * 4 + 0] += pr[i] * vv.x;
                    o[i][m * 4 + 1] += pr[i] * vv.y;
                    o[i][m * 4 + 2] += pr[i] * vv.z;
                    o[i][m * 4 + 3] += pr[i] * vv.w;
                }
            }
        }
        __syncthreads();
    }

#pragma unroll
    for (int i = 0; i < 4; i++) {
        int qglob = qt * 64 + tq * 4 + i;
        if (qglob >= qlen) continue;
        float inv = 1.f / lrow[tq * 4 + i];
        size_t base = ((size_t)(qs0 + qglob) * NH + h) * HD;
#pragma unroll
        for (int m = 0; m < 4; m++) {
            float4 w;
            w.x = o[i][m * 4 + 0] * inv;
            w.y = o[i][m * 4 + 1] * inv;
            w.z = o[i][m * 4 + 2] * inv;
            w.w = o[i][m * 4 + 3] * inv;
            *(float4*)&g_o[base + tk * 4 + 32 * m] = w;
        }
    }
}

// ============================================================================
extern "C" void kernel_launch(void* const* d_in, const int* in_sizes, int n_in,
                              void* d_out, int out_size) {
    const float* x      = (const float*)d_in[0];
    const int*   pos    = (const int*)d_in[1];
    const int*   qstart = (const int*)d_in[2];
    const int*   qlens  = (const int*)d_in[3];
    const int*   kvlens = (const int*)d_in[4];
    const int*   boff   = (const int*)d_in[5];
    const float* pk     = (const float*)d_in[6];
    const float* pv     = (const float*)d_in[7];
    const float* Wq = (const float*)d_in[8];
    const float* bq = (const float*)d_in[9];
    const float* Wk = (const float*)d_in[10];
    const float* bk = (const float*)d_in[11];
    const float* Wv = (const float*)d_in[12];
    const float* bv = (const float*)d_in[13];
    const float* Wo = (const float*)d_in[14];
    const float* bo = (const float*)d_in[15];
    float* out = (float*)d_out;

    float *qp, *kp, *vp, *op;
    cudaGetSymbolAddress((void**)&qp, g_q);
    cudaGetSymbolAddress((void**)&kp, g_k);
    cudaGetSymbolAddress((void**)&vp, g_v);
    cudaGetSymbolAddress((void**)&op, g_o);
    __nv_bfloat16 *xhi, *xlo, *w1hi, *w1lo, *w2hi, *w2lo, *w3hi, *w3lo;
    cudaGetSymbolAddress((void**)&xhi, g_xhi);
    cudaGetSymbolAddress((void**)&xlo, g_xlo);
    cudaGetSymbolAddress((void**)&w1hi, g_w1hi);
    cudaGetSymbolAddress((void**)&w1lo, g_w1lo);
    cudaGetSymbolAddress((void**)&w2hi, g_w2hi);
    cudaGetSymbolAddress((void**)&w2lo, g_w2lo);
    cudaGetSymbolAddress((void**)&w3hi, g_w3hi);
    cudaGetSymbolAddress((void**)&w3lo, g_w3lo);

    cudaFuncSetAttribute(gemm3, cudaFuncAttributeMaxDynamicSharedMemorySize, GEMM_SMEM);
    cudaFuncSetAttribute(attn_kernel, cudaFuncAttributeMaxDynamicSharedMemorySize, ATTN_SMEM_BYTES);

    const int n4x = TT * HID / 4;
    const int n4w = HID * HID / 4;
    dim3 gg(HID / 128, TT / 128);   // (32, 24)

    init_freq_kernel<<<1, 64>>>();
    split_kernel<<<(n4x + 255) / 256, 256>>>(x, xhi, xlo, n4x);
    split_kernel<<<(n4w + 255) / 256, 256>>>(Wq, w1hi, w1lo, n4w);
    split_kernel<<<(n4w + 255) / 256, 256>>>(Wk, w2hi, w2lo, n4w);
    split_kernel<<<(n4w + 255) / 256, 256>>>(Wv, w3hi, w3lo, n4w);

    gemm3<<<gg, 256, GEMM_SMEM>>>(xhi, xlo, w1hi, w1lo, bq, qp);
    gemm3<<<gg, 256, GEMM_SMEM>>>(xhi, xlo, w2hi, w2lo, bk, kp);
    gemm3<<<gg, 256, GEMM_SMEM>>>(xhi, xlo, w3hi, w3lo, bv, vp);

    rope_kernel<<<(TT * NH * 64 + 255) / 256, 256>>>(pos);
    attn_kernel<<<dim3(16, NH, NBAT), 128, ATTN_SMEM_BYTES>>>(pk, pv, qstart, qlens,
                                                              kvlens, boff);

    // reuse W1 buffers for Wo, x buffers for attention output
    split_kernel<<<(n4w + 255) / 256, 256>>>(Wo, w1hi, w1lo, n4w);
    split_kernel<<<(n4x + 255) / 256, 256>>>(op, xhi, xlo, n4x);
    gemm3<<<gg, 256, GEMM_SMEM>>>(xhi, xlo, w1hi, w1lo, bo, out);
}